// round 8
// baseline (speedup 1.0000x reference)
#include <cuda_runtime.h>
#include <cuda_fp16.h>
#include <mma.h>
#include <math.h>

using namespace nvcuda;

#define NMAX   100000
#define EMAX   1600000

// Static scratch ~59 MB.
__device__ float g_y[(size_t)NMAX * 128];   // persistent feature buffer
__device__ float g_dinv[NMAX];
__device__ int   g_dc[2 * NMAX];            // [0:N) deg, [N:2N) cursor — one memset
__device__ int   g_rowptr[NMAX];
__device__ int   g_csr[EMAX];
// split-fp16 weights (hi + lo residual)
__device__ __half g_w2h[128 * 64], g_w2l[128 * 64];
__device__ __half g_w3h[64 * 64],  g_w3l[64 * 64];

// ---------------- degree count + fused weight convert ----------------
__global__ void k_deg_count(const int* __restrict__ dst, int E,
                            const float* __restrict__ W2, const float* __restrict__ W3) {
    int e = blockIdx.x * blockDim.x + threadIdx.x;
    if (e < E) atomicAdd(&g_dc[__ldg(dst + e)], 1);
    if (blockIdx.x < 32) {  // 32*256 = 8192 >= 128*64
        int i = blockIdx.x * blockDim.x + threadIdx.x;
        if (i < 128 * 64) {
            float w = W2[i];
            __half h = __float2half_rn(w);
            g_w2h[i] = h;
            g_w2l[i] = __float2half_rn(w - __half2float(h));
        }
        if (i < 64 * 64) {
            float w = W3[i];
            __half h = __float2half_rn(w);
            g_w3h[i] = h;
            g_w3l[i] = __float2half_rn(w - __half2float(h));
        }
    }
}

// ---------------- single-block chunked exclusive scan (+dinv) ----------------
__global__ void k_scan_one(int n) {
    __shared__ int wsums[32];
    const int t = threadIdx.x;               // 1024 threads
    const int K = (n + 1023) >> 10;
    const int beg = t * K;
    const int endi = min(beg + K, n);

    int s = 0;
    for (int i = beg; i < endi; ++i) s += g_dc[i];

    int lane = t & 31, wid = t >> 5;
    int incl = s;
#pragma unroll
    for (int o = 1; o < 32; o <<= 1) {
        int u = __shfl_up_sync(0xffffffffu, incl, o);
        if (lane >= o) incl += u;
    }
    if (lane == 31) wsums[wid] = incl;
    __syncthreads();
    if (wid == 0) {
        int v = wsums[lane];
#pragma unroll
        for (int o = 1; o < 32; o <<= 1) {
            int u = __shfl_up_sync(0xffffffffu, v, o);
            if (lane >= o) v += u;
        }
        wsums[lane] = v;
    }
    __syncthreads();
    int run = (wid ? wsums[wid - 1] : 0) + incl - s;  // exclusive offset
    for (int i = beg; i < endi; ++i) {
        int d = g_dc[i];
        g_rowptr[i] = run;
        run += d;
        g_dinv[i] = rsqrtf((float)(d + 1));  // +1 self loop
    }
}

// ---------------- CSR placement ----------------
__global__ void k_place(const int* __restrict__ src, const int* __restrict__ dst, int E) {
    int e = blockIdx.x * blockDim.x + threadIdx.x;
    if (e >= E) return;
    int d = __ldg(dst + e);
    int pos = g_rowptr[d] + atomicAdd(&g_dc[NMAX + d], 1);
    g_csr[pos] = __ldg(src + e);
}

// ---------------- layer-1 pre-scale (fp16) ----------------
__global__ void k_xscale(const float* __restrict__ x, __half2* __restrict__ xs, int n) {
    int idx = blockIdx.x * blockDim.x + threadIdx.x;
    if (idx >= n * 8) return;
    int r = idx >> 3, p = idx & 7;
    float dv = g_dinv[r];
    int c0 = 2 * p, c1 = 2 * p + 1;
    float v0 = (c0 < 13) ? x[r * 13 + c0] * dv : 0.0f;
    float v1 = (c1 < 13) ? x[r * 13 + c1] * dv : 0.0f;
    xs[idx] = __floats2half2_rn(v0, v1);
}

// ---------------- 13(16)-ch aggregation, fp16 rows, 4 neighbors/step ----------------
__global__ void k_agg13(const __half2* __restrict__ xs, float* __restrict__ xa, int n) {
    int node = blockIdx.x * (blockDim.x >> 5) + (threadIdx.x >> 5);
    int lane = threadIdx.x & 31;
    if (node >= n) return;
    const int qw = lane >> 3;
    const int cl = lane & 7;

    float ax = 0.0f, ay = 0.0f;
    if (qw == 0) {
        float2 f = __half22float2(xs[node * 8 + cl]);
        ax = f.x; ay = f.y;
    }
    int start = g_rowptr[node];
    int end = start + g_dc[node];

    for (int j0 = start; j0 < end; j0 += 32) {
        int idx = 0;
        if (j0 + lane < end) idx = __ldg(&g_csr[j0 + lane]);
        int cnt = min(32, end - j0);
        int t = 0;
        for (; t + 8 <= cnt; t += 8) {
            int s0 = __shfl_sync(0xffffffffu, idx, t + qw);
            int s1 = __shfl_sync(0xffffffffu, idx, t + 4 + qw);
            float2 v0 = __half22float2(__ldg(&xs[s0 * 8 + cl]));
            float2 v1 = __half22float2(__ldg(&xs[s1 * 8 + cl]));
            ax += v0.x + v1.x;
            ay += v0.y + v1.y;
        }
        for (; t + 4 <= cnt; t += 4) {
            int s = __shfl_sync(0xffffffffu, idx, t + qw);
            float2 v = __half22float2(__ldg(&xs[s * 8 + cl]));
            ax += v.x; ay += v.y;
        }
        int rem = cnt - t;
        if (rem > 0) {
            int s = __shfl_sync(0xffffffffu, idx, t + (qw < rem ? qw : 0));
            if (qw < rem) {
                float2 v = __half22float2(__ldg(&xs[s * 8 + cl]));
                ax += v.x; ay += v.y;
            }
        }
    }
    ax += __shfl_down_sync(0xffffffffu, ax, 16);
    ay += __shfl_down_sync(0xffffffffu, ay, 16);
    ax += __shfl_down_sync(0xffffffffu, ax, 8);
    ay += __shfl_down_sync(0xffffffffu, ay, 8);
    if (lane < 8) {
        float dv = g_dinv[node];
        *(float2*)&xa[node * 16 + cl * 2] = make_float2(ax * dv, ay * dv);
    }
}

// ---------------- layer-1 scalar GEMM (fp32 in, fp16 out, bias+relu) ----------------
__global__ void k_gemm_l1(const float* __restrict__ x,
                          const float* __restrict__ W,
                          const float* __restrict__ bias,
                          __half* __restrict__ hout, int n) {
    constexpr int TB = 256, CIN = 13, COUT = 128, ROWS = 32, ITER = 8;
    constexpr int CPT = COUT / 16;  // 8
    constexpr int SXS = 20;
    __shared__ float Ws[CIN * COUT];
    __shared__ float xs[ROWS * SXS];

    {
        const float4* Wv = (const float4*)W;
        for (int i = threadIdx.x; i < CIN * COUT / 4; i += TB)
            ((float4*)Ws)[i] = Wv[i];
    }
    const int cg = threadIdx.x & 15;
    const int rg = threadIdx.x >> 4;
    float bb[CPT];
#pragma unroll
    for (int j = 0; j < CPT; ++j) bb[j] = __ldg(bias + cg * CPT + j);

    for (int it = 0; it < ITER; ++it) {
        const int rowbase = (blockIdx.x * ITER + it) * ROWS;
        if (rowbase >= n) break;
        float acc[2][CPT];
#pragma unroll
        for (int j = 0; j < CPT; ++j) { acc[0][j] = bb[j]; acc[1][j] = bb[j]; }

        __syncthreads();
        for (int i = threadIdx.x; i < ROWS * CIN; i += TB) {
            int row = i / CIN, c = i % CIN;
            int rr = rowbase + row;
            xs[row * SXS + c] = (rr < n) ? x[(size_t)rr * 16 + c] : 0.0f;
        }
        __syncthreads();
        const float* wbase = Ws + cg * CPT;
        const float* x0 = xs + (2 * rg) * SXS;
        const float* x1 = x0 + SXS;
#pragma unroll
        for (int k = 0; k < CIN; ++k) {
            float a0 = x0[k], a1 = x1[k];
            const float4* wr = (const float4*)(wbase + k * COUT);
#pragma unroll
            for (int j4 = 0; j4 < CPT / 4; ++j4) {
                float4 w = wr[j4];
                acc[0][j4 * 4 + 0] = fmaf(a0, w.x, acc[0][j4 * 4 + 0]);
                acc[0][j4 * 4 + 1] = fmaf(a0, w.y, acc[0][j4 * 4 + 1]);
                acc[0][j4 * 4 + 2] = fmaf(a0, w.z, acc[0][j4 * 4 + 2]);
                acc[0][j4 * 4 + 3] = fmaf(a0, w.w, acc[0][j4 * 4 + 3]);
                acc[1][j4 * 4 + 0] = fmaf(a1, w.x, acc[1][j4 * 4 + 0]);
                acc[1][j4 * 4 + 1] = fmaf(a1, w.y, acc[1][j4 * 4 + 1]);
                acc[1][j4 * 4 + 2] = fmaf(a1, w.z, acc[1][j4 * 4 + 2]);
                acc[1][j4 * 4 + 3] = fmaf(a1, w.w, acc[1][j4 * 4 + 3]);
            }
        }
#pragma unroll
        for (int rr = 0; rr < 2; ++rr) {
            int r = rowbase + 2 * rg + rr;
            if (r >= n) continue;
            __half2* hp = (__half2*)(hout + (size_t)r * 128 + cg * CPT);
#pragma unroll
            for (int j2 = 0; j2 < CPT / 2; ++j2)
                hp[j2] = __floats2half2_rn(fmaxf(acc[rr][j2 * 2], 0.0f),
                                           fmaxf(acc[rr][j2 * 2 + 1], 0.0f));
        }
    }
}

// ---------------- tensor-core GEMM (fp16 in, split-fp16 W, fp32 acc, fp16*dinv out) ----------------
template <int CIN>
__global__ void k_gemm_tc(const __half* __restrict__ A, int lda,
                          const __half* __restrict__ Whi, const __half* __restrict__ Wlo,
                          __half* __restrict__ hout, int ldo, int n) {
    constexpr int KT = CIN / 16;
    constexpr int WS_BYTES = 2 * CIN * 64 * 2;
    constexpr int EP_BYTES = 8 * 16 * 68 * 4;
    constexpr int SM_BYTES = (WS_BYTES > EP_BYTES) ? WS_BYTES : EP_BYTES;
    __shared__ __align__(16) unsigned char smem_raw[SM_BYTES];
    __half* Ws = (__half*)smem_raw;
    float* ep = (float*)smem_raw;

    for (int i = threadIdx.x; i < CIN * 64; i += 256) {
        Ws[i] = Whi[i];
        Ws[CIN * 64 + i] = Wlo[i];
    }
    __syncthreads();

    const int warp = threadIdx.x >> 5;
    const int lane = threadIdx.x & 31;
    const int rowbase = blockIdx.x * 128 + warp * 16;

    wmma::fragment<wmma::accumulator, 16, 16, 16, float> acc[4];
#pragma unroll
    for (int nt = 0; nt < 4; ++nt) wmma::fill_fragment(acc[nt], 0.0f);

    if (rowbase < n) {
#pragma unroll
        for (int kt = 0; kt < KT; ++kt) {
            wmma::fragment<wmma::matrix_a, 16, 16, 16, __half, wmma::row_major> af;
            wmma::load_matrix_sync(af, A + (size_t)rowbase * lda + kt * 16, lda);
#pragma unroll
            for (int nt = 0; nt < 4; ++nt) {
                wmma::fragment<wmma::matrix_b, 16, 16, 16, __half, wmma::row_major> bh, bl;
                wmma::load_matrix_sync(bh, Ws + kt * 16 * 64 + nt * 16, 64);
                wmma::mma_sync(acc[nt], af, bh, acc[nt]);
                wmma::load_matrix_sync(bl, Ws + CIN * 64 + kt * 16 * 64 + nt * 16, 64);
                wmma::mma_sync(acc[nt], af, bl, acc[nt]);
            }
        }
    }
    __syncthreads();

    float* myep = ep + warp * 16 * 68;
#pragma unroll
    for (int nt = 0; nt < 4; ++nt)
        wmma::store_matrix_sync(myep + nt * 16, acc[nt], 68, wmma::mem_row_major);
    __syncwarp();

    if (rowbase < n) {
#pragma unroll
        for (int r = 0; r < 16; ++r) {
            int gr = rowbase + r;
            if (gr >= n) break;
            float dv = g_dinv[gr];
            float vx = myep[r * 68 + lane * 2];
            float vy = myep[r * 68 + lane * 2 + 1];
            ((__half2*)(hout + (size_t)gr * ldo))[lane] = __floats2half2_rn(vx * dv, vy * dv);
        }
    }
}

// ---------------- 64-ch aggregation over fp16 hs + bias (+relu) ----------------
template <bool RELU, bool OUT_HALF>
__global__ void k_aggh(const __half2* __restrict__ hs, int sH2,
                       const float* __restrict__ b,
                       void* __restrict__ yout, int ystride, int n) {
    int node = blockIdx.x * (blockDim.x >> 5) + (threadIdx.x >> 5);
    int lane = threadIdx.x & 31;
    if (node >= n) return;

    float2 f = __half22float2(hs[(size_t)node * sH2 + lane]);
    float ax = f.x, ay = f.y;
    int start = g_rowptr[node];
    int end = start + g_dc[node];

    for (int j0 = start; j0 < end; j0 += 32) {
        int idx = 0;
        if (j0 + lane < end) idx = __ldg(&g_csr[j0 + lane]);
        int cnt = min(32, end - j0);
        int t = 0;
        for (; t + 8 <= cnt; t += 8) {
            float2 v[8];
#pragma unroll
            for (int u = 0; u < 8; ++u) {
                int s = __shfl_sync(0xffffffffu, idx, t + u);
                v[u] = __half22float2(__ldg(&hs[(size_t)s * sH2 + lane]));
            }
#pragma unroll
            for (int u = 0; u < 8; ++u) { ax += v[u].x; ay += v[u].y; }
        }
        for (; t < cnt; ++t) {
            int s = __shfl_sync(0xffffffffu, idx, t);
            float2 v = __half22float2(__ldg(&hs[(size_t)s * sH2 + lane]));
            ax += v.x; ay += v.y;
        }
    }

    float dv = g_dinv[node];
    float2 bb = *(const float2*)(b + lane * 2);
    float ox = fmaf(ax, dv, bb.x);
    float oy = fmaf(ay, dv, bb.y);
    if (RELU) { ox = fmaxf(ox, 0.0f); oy = fmaxf(oy, 0.0f); }
    if (OUT_HALF) {
        ((__half2*)yout)[(size_t)node * (ystride / 2) + lane] = __floats2half2_rn(ox, oy);
    } else {
        *(float2*)&((float*)yout)[(size_t)node * ystride + lane * 2] = make_float2(ox, oy);
    }
}

// ---------------- launch ----------------
extern "C" void kernel_launch(void* const* d_in, const int* in_sizes, int n_in,
                              void* d_out, int out_size) {
    const float* x  = (const float*)d_in[0];
    const int*   ei = (const int*)d_in[1];
    const float* W1 = (const float*)d_in[2];
    const float* b1 = (const float*)d_in[3];
    const float* W2 = (const float*)d_in[4];
    const float* b2 = (const float*)d_in[5];
    const float* W3 = (const float*)d_in[6];
    const float* b3 = (const float*)d_in[7];
    float* dout = (float*)d_out;

    const int n = in_sizes[0] / 13;
    const int E = in_sizes[1] / 2;
    const int* src = ei;
    const int* dst = ei + E;

    const int TB = 256;
    auto cdiv = [](long long a, long long b) { return (int)((a + b - 1) / b); };
    const int g_aggg = cdiv(n, TB / 32);
    const int g_tc = cdiv(n, 128);

    float* y = nullptr;
    cudaGetSymbolAddress((void**)&y, g_y);
    int* dcp = nullptr;
    cudaGetSymbolAddress((void**)&dcp, g_dc);
    __half *w2h, *w2l, *w3h, *w3l;
    cudaGetSymbolAddress((void**)&w2h, g_w2h);
    cudaGetSymbolAddress((void**)&w2l, g_w2l);
    cudaGetSymbolAddress((void**)&w3h, g_w3h);
    cudaGetSymbolAddress((void**)&w3l, g_w3l);

    // Buffer plan (sequential stream, dead-before-overwrite):
    __half2* xs_h2 = (__half2*)dout;                    // N x 8 half2
    float*   xa    = dout + (size_t)n * 8;              // N x 16 fp32
    __half*  y1h   = (__half*)y;                        // N x 128 fp16
    __half*  hs2   = (__half*)dout;                     // N x 64 fp16
    __half*  y2h   = (__half*)(y + (size_t)NMAX * 64);  // N x 64 fp16
    __half*  hs3   = (__half*)y;                        // N x 64 fp16 (over dead y1h)

    // ---- CSR build (4 nodes) ----
    cudaMemsetAsync(dcp, 0, (size_t)2 * NMAX * 4, 0);           // node 1
    k_deg_count<<<cdiv(E, TB), TB>>>(dst, E, W2, W3);           // node 2 (+wconv)
    k_scan_one<<<1, 1024>>>(n);                                 // node 3 (+dinv)
    k_place<<<cdiv(E, TB), TB>>>(src, dst, E);                  // node 4

    // ---- layer 1 ----
    k_xscale<<<cdiv((long long)n * 8, TB), TB>>>(x, xs_h2, n);  // node 5
    k_agg13<<<g_aggg, TB>>>(xs_h2, xa, n);                      // node 6 <- ncu window
    k_gemm_l1<<<cdiv(n, 32 * 8), TB>>>(xa, W1, b1, y1h, n);     // node 7

    // ---- layer 2 ----
    k_gemm_tc<128><<<g_tc, TB>>>(y1h, 128, w2h, w2l, hs2, 64, n);
    k_aggh<true, true><<<g_aggg, TB>>>((const __half2*)hs2, 32, b2, y2h, 64, n);

    // ---- layer 3 ----
    k_gemm_tc<64><<<g_tc, TB>>>(y2h, 64, w3h, w3l, hs3, 64, n);
    k_aggh<false, false><<<g_aggg, TB>>>((const __half2*)hs3, 32, b3, dout, 64, n);
}

// round 9
// speedup vs baseline: 1.4595x; 1.4595x over previous
#include <cuda_runtime.h>
#include <cuda_fp16.h>
#include <mma.h>
#include <math.h>

using namespace nvcuda;

#define NMAX   100000
#define EMAX   1600000
#define SCAN_B 512

// Static scratch ~59 MB.
__device__ float g_y[(size_t)NMAX * 128];   // persistent feature buffer
__device__ float g_dinv[NMAX];
__device__ int   g_dc[2 * NMAX];            // [0:N) deg, [N:2N) cursor — one memset
__device__ int   g_rowptr[NMAX];
__device__ int   g_csr[EMAX];
__device__ int   g_bsums[1024];
// split-fp16 weights (hi + lo residual)
__device__ __half g_w2h[128 * 64], g_w2l[128 * 64];
__device__ __half g_w3h[64 * 64],  g_w3l[64 * 64];

// ---------------- degree count + fused weight convert ----------------
__global__ void k_deg_count(const int* __restrict__ dst, int E,
                            const float* __restrict__ W2, const float* __restrict__ W3) {
    int e = blockIdx.x * blockDim.x + threadIdx.x;
    if (e < E) atomicAdd(&g_dc[__ldg(dst + e)], 1);
    if (blockIdx.x < 32) {  // 32*256 = 8192 >= 128*64
        int i = blockIdx.x * blockDim.x + threadIdx.x;
        if (i < 128 * 64) {
            float w = W2[i];
            __half h = __float2half_rn(w);
            g_w2h[i] = h;
            g_w2l[i] = __float2half_rn(w - __half2float(h));
        }
        if (i < 64 * 64) {
            float w = W3[i];
            __half h = __float2half_rn(w);
            g_w3h[i] = h;
            g_w3l[i] = __float2half_rn(w - __half2float(h));
        }
    }
}

// ---------------- multi-block warp-shuffle scan (3 kernels) + dinv ----------------
__global__ void k_scan1(int n) {
    __shared__ int wsum[SCAN_B / 32];
    int gid = blockIdx.x * SCAN_B + threadIdx.x;
    int v = (gid < n) ? g_dc[gid] : 0;
    if (gid < n) g_dinv[gid] = rsqrtf((float)(v + 1));  // +1 self loop
    int lane = threadIdx.x & 31, wid = threadIdx.x >> 5;
    int incl = v;
#pragma unroll
    for (int o = 1; o < 32; o <<= 1) {
        int t = __shfl_up_sync(0xffffffffu, incl, o);
        if (lane >= o) incl += t;
    }
    if (lane == 31) wsum[wid] = incl;
    __syncthreads();
    if (wid == 0) {
        int s = (lane < SCAN_B / 32) ? wsum[lane] : 0;
#pragma unroll
        for (int o = 1; o < SCAN_B / 32; o <<= 1) {
            int t = __shfl_up_sync(0xffffffffu, s, o);
            if (lane >= o) s += t;
        }
        if (lane < SCAN_B / 32) wsum[lane] = s;
    }
    __syncthreads();
    int off = wid ? wsum[wid - 1] : 0;
    if (gid < n) g_rowptr[gid] = off + incl - v;  // exclusive
    if (threadIdx.x == SCAN_B - 1) g_bsums[blockIdx.x] = off + incl;
}

__global__ void k_scan2(int nb) {  // single block, nb <= SCAN_B
    __shared__ int sm[SCAN_B];
    int v = (threadIdx.x < nb) ? g_bsums[threadIdx.x] : 0;
    sm[threadIdx.x] = v;
    __syncthreads();
    for (int off = 1; off < SCAN_B; off <<= 1) {
        int t = (threadIdx.x >= off) ? sm[threadIdx.x - off] : 0;
        __syncthreads();
        sm[threadIdx.x] += t;
        __syncthreads();
    }
    if (threadIdx.x < nb) g_bsums[threadIdx.x] = sm[threadIdx.x];  // inclusive
}

__global__ void k_scan3(int n) {
    int gid = blockIdx.x * SCAN_B + threadIdx.x;
    if (gid >= n || blockIdx.x == 0) return;
    g_rowptr[gid] += g_bsums[blockIdx.x - 1];
}

// ---------------- CSR placement ----------------
__global__ void k_place(const int* __restrict__ src, const int* __restrict__ dst, int E) {
    int e = blockIdx.x * blockDim.x + threadIdx.x;
    if (e >= E) return;
    int d = __ldg(dst + e);
    int pos = g_rowptr[d] + atomicAdd(&g_dc[NMAX + d], 1);
    g_csr[pos] = __ldg(src + e);
}

// ---------------- layer-1 pre-scale (fp16) ----------------
__global__ void k_xscale(const float* __restrict__ x, __half2* __restrict__ xs, int n) {
    int idx = blockIdx.x * blockDim.x + threadIdx.x;
    if (idx >= n * 8) return;
    int r = idx >> 3, p = idx & 7;
    float dv = g_dinv[r];
    int c0 = 2 * p, c1 = 2 * p + 1;
    float v0 = (c0 < 13) ? x[r * 13 + c0] * dv : 0.0f;
    float v1 = (c1 < 13) ? x[r * 13 + c1] * dv : 0.0f;
    xs[idx] = __floats2half2_rn(v0, v1);
}

// ---------------- 13(16)-ch aggregation, fp16 rows, 4 neighbors/step ----------------
__global__ void k_agg13(const __half2* __restrict__ xs, float* __restrict__ xa, int n) {
    int node = blockIdx.x * (blockDim.x >> 5) + (threadIdx.x >> 5);
    int lane = threadIdx.x & 31;
    if (node >= n) return;
    const int qw = lane >> 3;
    const int cl = lane & 7;

    float ax = 0.0f, ay = 0.0f;
    if (qw == 0) {
        float2 f = __half22float2(xs[node * 8 + cl]);
        ax = f.x; ay = f.y;
    }
    int start = g_rowptr[node];
    int end = start + g_dc[node];

    for (int j0 = start; j0 < end; j0 += 32) {
        int idx = 0;
        if (j0 + lane < end) idx = __ldg(&g_csr[j0 + lane]);
        int cnt = min(32, end - j0);
        int t = 0;
        for (; t + 8 <= cnt; t += 8) {
            int s0 = __shfl_sync(0xffffffffu, idx, t + qw);
            int s1 = __shfl_sync(0xffffffffu, idx, t + 4 + qw);
            float2 v0 = __half22float2(__ldg(&xs[s0 * 8 + cl]));
            float2 v1 = __half22float2(__ldg(&xs[s1 * 8 + cl]));
            ax += v0.x + v1.x;
            ay += v0.y + v1.y;
        }
        for (; t + 4 <= cnt; t += 4) {
            int s = __shfl_sync(0xffffffffu, idx, t + qw);
            float2 v = __half22float2(__ldg(&xs[s * 8 + cl]));
            ax += v.x; ay += v.y;
        }
        int rem = cnt - t;
        if (rem > 0) {
            int s = __shfl_sync(0xffffffffu, idx, t + (qw < rem ? qw : 0));
            if (qw < rem) {
                float2 v = __half22float2(__ldg(&xs[s * 8 + cl]));
                ax += v.x; ay += v.y;
            }
        }
    }
    ax += __shfl_down_sync(0xffffffffu, ax, 16);
    ay += __shfl_down_sync(0xffffffffu, ay, 16);
    ax += __shfl_down_sync(0xffffffffu, ax, 8);
    ay += __shfl_down_sync(0xffffffffu, ay, 8);
    if (lane < 8) {
        float dv = g_dinv[node];
        *(float2*)&xa[node * 16 + cl * 2] = make_float2(ax * dv, ay * dv);
    }
}

// ---------------- layer-1 scalar GEMM (fp32 in, fp16 out, bias+relu) ----------------
__global__ void k_gemm_l1(const float* __restrict__ x,
                          const float* __restrict__ W,
                          const float* __restrict__ bias,
                          __half* __restrict__ hout, int n) {
    constexpr int TB = 256, CIN = 13, COUT = 128, ROWS = 32, ITER = 8;
    constexpr int CPT = COUT / 16;  // 8
    constexpr int SXS = 20;
    __shared__ float Ws[CIN * COUT];
    __shared__ float xs[ROWS * SXS];

    {
        const float4* Wv = (const float4*)W;
        for (int i = threadIdx.x; i < CIN * COUT / 4; i += TB)
            ((float4*)Ws)[i] = Wv[i];
    }
    const int cg = threadIdx.x & 15;
    const int rg = threadIdx.x >> 4;
    float bb[CPT];
#pragma unroll
    for (int j = 0; j < CPT; ++j) bb[j] = __ldg(bias + cg * CPT + j);

    for (int it = 0; it < ITER; ++it) {
        const int rowbase = (blockIdx.x * ITER + it) * ROWS;
        if (rowbase >= n) break;
        float acc[2][CPT];
#pragma unroll
        for (int j = 0; j < CPT; ++j) { acc[0][j] = bb[j]; acc[1][j] = bb[j]; }

        __syncthreads();
        for (int i = threadIdx.x; i < ROWS * CIN; i += TB) {
            int row = i / CIN, c = i % CIN;
            int rr = rowbase + row;
            xs[row * SXS + c] = (rr < n) ? x[(size_t)rr * 16 + c] : 0.0f;
        }
        __syncthreads();
        const float* wbase = Ws + cg * CPT;
        const float* x0 = xs + (2 * rg) * SXS;
        const float* x1 = x0 + SXS;
#pragma unroll
        for (int k = 0; k < CIN; ++k) {
            float a0 = x0[k], a1 = x1[k];
            const float4* wr = (const float4*)(wbase + k * COUT);
#pragma unroll
            for (int j4 = 0; j4 < CPT / 4; ++j4) {
                float4 w = wr[j4];
                acc[0][j4 * 4 + 0] = fmaf(a0, w.x, acc[0][j4 * 4 + 0]);
                acc[0][j4 * 4 + 1] = fmaf(a0, w.y, acc[0][j4 * 4 + 1]);
                acc[0][j4 * 4 + 2] = fmaf(a0, w.z, acc[0][j4 * 4 + 2]);
                acc[0][j4 * 4 + 3] = fmaf(a0, w.w, acc[0][j4 * 4 + 3]);
                acc[1][j4 * 4 + 0] = fmaf(a1, w.x, acc[1][j4 * 4 + 0]);
                acc[1][j4 * 4 + 1] = fmaf(a1, w.y, acc[1][j4 * 4 + 1]);
                acc[1][j4 * 4 + 2] = fmaf(a1, w.z, acc[1][j4 * 4 + 2]);
                acc[1][j4 * 4 + 3] = fmaf(a1, w.w, acc[1][j4 * 4 + 3]);
            }
        }
#pragma unroll
        for (int rr = 0; rr < 2; ++rr) {
            int r = rowbase + 2 * rg + rr;
            if (r >= n) continue;
            __half2* hp = (__half2*)(hout + (size_t)r * 128 + cg * CPT);
#pragma unroll
            for (int j2 = 0; j2 < CPT / 2; ++j2)
                hp[j2] = __floats2half2_rn(fmaxf(acc[rr][j2 * 2], 0.0f),
                                           fmaxf(acc[rr][j2 * 2 + 1], 0.0f));
        }
    }
}

// ---------------- tensor-core GEMM (fp16 in, split-fp16 W, fp32 acc, fp16*dinv out) ----------------
template <int CIN>
__global__ void k_gemm_tc(const __half* __restrict__ A, int lda,
                          const __half* __restrict__ Whi, const __half* __restrict__ Wlo,
                          __half* __restrict__ hout, int ldo, int n) {
    constexpr int KT = CIN / 16;
    constexpr int WS_BYTES = 2 * CIN * 64 * 2;
    constexpr int EP_BYTES = 8 * 16 * 68 * 4;
    constexpr int SM_BYTES = (WS_BYTES > EP_BYTES) ? WS_BYTES : EP_BYTES;
    __shared__ __align__(16) unsigned char smem_raw[SM_BYTES];
    __half* Ws = (__half*)smem_raw;
    float* ep = (float*)smem_raw;

    for (int i = threadIdx.x; i < CIN * 64; i += 256) {
        Ws[i] = Whi[i];
        Ws[CIN * 64 + i] = Wlo[i];
    }
    __syncthreads();

    const int warp = threadIdx.x >> 5;
    const int lane = threadIdx.x & 31;
    const int rowbase = blockIdx.x * 128 + warp * 16;

    wmma::fragment<wmma::accumulator, 16, 16, 16, float> acc[4];
#pragma unroll
    for (int nt = 0; nt < 4; ++nt) wmma::fill_fragment(acc[nt], 0.0f);

    if (rowbase < n) {
#pragma unroll
        for (int kt = 0; kt < KT; ++kt) {
            wmma::fragment<wmma::matrix_a, 16, 16, 16, __half, wmma::row_major> af;
            wmma::load_matrix_sync(af, A + (size_t)rowbase * lda + kt * 16, lda);
#pragma unroll
            for (int nt = 0; nt < 4; ++nt) {
                wmma::fragment<wmma::matrix_b, 16, 16, 16, __half, wmma::row_major> bh, bl;
                wmma::load_matrix_sync(bh, Ws + kt * 16 * 64 + nt * 16, 64);
                wmma::mma_sync(acc[nt], af, bh, acc[nt]);
                wmma::load_matrix_sync(bl, Ws + CIN * 64 + kt * 16 * 64 + nt * 16, 64);
                wmma::mma_sync(acc[nt], af, bl, acc[nt]);
            }
        }
    }
    __syncthreads();

    float* myep = ep + warp * 16 * 68;
#pragma unroll
    for (int nt = 0; nt < 4; ++nt)
        wmma::store_matrix_sync(myep + nt * 16, acc[nt], 68, wmma::mem_row_major);
    __syncwarp();

    if (rowbase < n) {
#pragma unroll
        for (int r = 0; r < 16; ++r) {
            int gr = rowbase + r;
            if (gr >= n) break;
            float dv = g_dinv[gr];
            float vx = myep[r * 68 + lane * 2];
            float vy = myep[r * 68 + lane * 2 + 1];
            ((__half2*)(hout + (size_t)gr * ldo))[lane] = __floats2half2_rn(vx * dv, vy * dv);
        }
    }
}

// ---------------- 64-ch aggregation over fp16 hs + bias (+relu) ----------------
template <bool RELU, bool OUT_HALF>
__global__ void k_aggh(const __half2* __restrict__ hs, int sH2,
                       const float* __restrict__ b,
                       void* __restrict__ yout, int ystride, int n) {
    int node = blockIdx.x * (blockDim.x >> 5) + (threadIdx.x >> 5);
    int lane = threadIdx.x & 31;
    if (node >= n) return;

    float2 f = __half22float2(hs[(size_t)node * sH2 + lane]);
    float ax = f.x, ay = f.y;
    int start = g_rowptr[node];
    int end = start + g_dc[node];

    for (int j0 = start; j0 < end; j0 += 32) {
        int idx = 0;
        if (j0 + lane < end) idx = __ldg(&g_csr[j0 + lane]);
        int cnt = min(32, end - j0);
        int t = 0;
        for (; t + 8 <= cnt; t += 8) {
            float2 v[8];
#pragma unroll
            for (int u = 0; u < 8; ++u) {
                int s = __shfl_sync(0xffffffffu, idx, t + u);
                v[u] = __half22float2(__ldg(&hs[(size_t)s * sH2 + lane]));
            }
#pragma unroll
            for (int u = 0; u < 8; ++u) { ax += v[u].x; ay += v[u].y; }
        }
        if (t + 4 <= cnt) {  // 4-wide intermediate batch shortens the serial tail
            float2 v[4];
#pragma unroll
            for (int u = 0; u < 4; ++u) {
                int s = __shfl_sync(0xffffffffu, idx, t + u);
                v[u] = __half22float2(__ldg(&hs[(size_t)s * sH2 + lane]));
            }
#pragma unroll
            for (int u = 0; u < 4; ++u) { ax += v[u].x; ay += v[u].y; }
            t += 4;
        }
        for (; t < cnt; ++t) {
            int s = __shfl_sync(0xffffffffu, idx, t);
            float2 v = __half22float2(__ldg(&hs[(size_t)s * sH2 + lane]));
            ax += v.x; ay += v.y;
        }
    }

    float dv = g_dinv[node];
    float2 bb = *(const float2*)(b + lane * 2);
    float ox = fmaf(ax, dv, bb.x);
    float oy = fmaf(ay, dv, bb.y);
    if (RELU) { ox = fmaxf(ox, 0.0f); oy = fmaxf(oy, 0.0f); }
    if (OUT_HALF) {
        ((__half2*)yout)[(size_t)node * (ystride / 2) + lane] = __floats2half2_rn(ox, oy);
    } else {
        *(float2*)&((float*)yout)[(size_t)node * ystride + lane * 2] = make_float2(ox, oy);
    }
}

// ---------------- launch ----------------
extern "C" void kernel_launch(void* const* d_in, const int* in_sizes, int n_in,
                              void* d_out, int out_size) {
    const float* x  = (const float*)d_in[0];
    const int*   ei = (const int*)d_in[1];
    const float* W1 = (const float*)d_in[2];
    const float* b1 = (const float*)d_in[3];
    const float* W2 = (const float*)d_in[4];
    const float* b2 = (const float*)d_in[5];
    const float* W3 = (const float*)d_in[6];
    const float* b3 = (const float*)d_in[7];
    float* dout = (float*)d_out;

    const int n = in_sizes[0] / 13;
    const int E = in_sizes[1] / 2;
    const int* src = ei;
    const int* dst = ei + E;

    const int TB = 256;
    auto cdiv = [](long long a, long long b) { return (int)((a + b - 1) / b); };
    const int g_aggg = cdiv(n, TB / 32);
    const int g_tc = cdiv(n, 128);
    const int nb = cdiv(n, SCAN_B);

    float* y = nullptr;
    cudaGetSymbolAddress((void**)&y, g_y);
    int* dcp = nullptr;
    cudaGetSymbolAddress((void**)&dcp, g_dc);
    __half *w2h, *w2l, *w3h, *w3l;
    cudaGetSymbolAddress((void**)&w2h, g_w2h);
    cudaGetSymbolAddress((void**)&w2l, g_w2l);
    cudaGetSymbolAddress((void**)&w3h, g_w3h);
    cudaGetSymbolAddress((void**)&w3l, g_w3l);

    // Buffer plan (sequential stream, dead-before-overwrite):
    __half2* xs_h2 = (__half2*)dout;                    // N x 8 half2
    float*   xa    = dout + (size_t)n * 8;              // N x 16 fp32
    __half*  y1h   = (__half*)y;                        // N x 128 fp16
    __half*  hs2   = (__half*)dout;                     // N x 64 fp16
    __half*  y2h   = (__half*)(y + (size_t)NMAX * 64);  // N x 64 fp16
    __half*  hs3   = (__half*)y;                        // N x 64 fp16 (over dead y1h)

    // ---- CSR build (6 nodes) ----
    cudaMemsetAsync(dcp, 0, (size_t)2 * NMAX * 4, 0);
    k_deg_count<<<cdiv(E, TB), TB>>>(dst, E, W2, W3);   // +wconv fused
    k_scan1<<<nb, SCAN_B>>>(n);                         // +dinv fused
    k_scan2<<<1, SCAN_B>>>(nb);
    k_scan3<<<nb, SCAN_B>>>(n);
    k_place<<<cdiv(E, TB), TB>>>(src, dst, E);

    // ---- layer 1 ----
    k_xscale<<<cdiv((long long)n * 8, TB), TB>>>(x, xs_h2, n);
    k_agg13<<<g_aggg, TB>>>(xs_h2, xa, n);
    k_gemm_l1<<<cdiv(n, 32 * 8), TB>>>(xa, W1, b1, y1h, n);

    // ---- layer 2 ----
    k_gemm_tc<128><<<g_tc, TB>>>(y1h, 128, w2h, w2l, hs2, 64, n);
    k_aggh<true, true><<<g_aggg, TB>>>((const __half2*)hs2, 32, b2, y2h, 64, n);

    // ---- layer 3 ----
    k_gemm_tc<64><<<g_tc, TB>>>(y2h, 64, w3h, w3l, hs3, 64, n);
    k_aggh<false, false><<<g_aggg, TB>>>((const __half2*)hs3, 32, b3, dout, 64, n);
}